// round 9
// baseline (speedup 1.0000x reference)
#include <cuda_runtime.h>
#include <cuda_fp16.h>
#include <math.h>

#define NMAX 100000
#define EMAX 3200000
#define F_IN 512
#define HID 16
#define NLAB 64

// ---------------- device scratch (no allocations allowed) ----------------
// ONLY referenced inside device code (GB300 ATS silently accepts host-shadow
// addresses — never pass these as kernel args).
__device__ float g_norm_src[NMAX];
__device__ float g_norm_dst[NMAX];
__device__ int   g_deg_out[NMAX];
__device__ int   g_deg_in[NMAX];
__device__ int   g_row_start[NMAX];
__device__ unsigned long long g_lb[512];   // lookback: (flag<<32)|value
__device__ int   g_csr[EMAX];
__device__ int   g_esrc[EMAX];
__device__ int   g_edst[EMAX];
__device__ int   g_slot[EMAX];
__device__ int   g_fmt;                    // 0=i64,1=i32,2=f32,3=f64
__device__ float g_hpre[NMAX * HID];       // X @ W1 (fp32, unscaled)
__device__ uint2 g_hpreh[NMAX * 4];        // (X@W1)*ns as half2 rows (32B)
__device__ uint2 g_hmidh[NMAX * 4];        // relu(...)*ns as half2 rows (32B)

// ---------------- f32x2 packed-FMA helpers ----------------
__device__ __forceinline__ unsigned long long pack2(float v) {
    unsigned long long r;
    asm("mov.b64 %0, {%1, %1};" : "=l"(r) : "f"(v));
    return r;
}
__device__ __forceinline__ void fma2(unsigned long long& acc,
                                     unsigned long long a,
                                     unsigned long long b) {
    asm("fma.rn.f32x2 %0, %1, %2, %0;" : "+l"(acc) : "l"(a), "l"(b));
}
__device__ __forceinline__ float2 unpack2(unsigned long long v) {
    float2 r;
    asm("mov.b64 {%0, %1}, %2;" : "=f"(r.x), "=f"(r.y) : "l"(v));
    return r;
}
__device__ __forceinline__ unsigned h2u(__half2 h) {
    return *(unsigned*)&h;
}
__device__ __forceinline__ uint2 pack_half4(float a, float b, float c, float d) {
    uint2 r;
    r.x = h2u(__floats2half2_rn(a, b));
    r.y = h2u(__floats2half2_rn(c, d));
    return r;
}

// ---------------- init: zero degrees + lookback + edge-dtype probe ----------------
__global__ void k_init(const void* __restrict__ src, int ecount, int n) {
    int i = blockIdx.x * blockDim.x + threadIdx.x;
    if (i < n) { g_deg_out[i] = 0; g_deg_in[i] = 0; }
    if (i < 512) g_lb[i] = 0ull;
    if (blockIdx.x == 0) {
        __shared__ int ok64, ok32, okf32, okf64;
        if (threadIdx.x == 0) { ok64 = 1; ok32 = 1; okf32 = 1; okf64 = 1; }
        __syncthreads();
        int nprobe = ecount < 1024 ? ecount : 1024;
        for (int e = threadIdx.x; e < nprobe; e += blockDim.x) {
            long long v64 = ((const long long*)src)[e];
            if (v64 < 0 || v64 >= (long long)n) atomicAnd(&ok64, 0);
            int v32 = ((const int*)src)[e];
            if (v32 < 0 || v32 >= n) atomicAnd(&ok32, 0);
            float f = ((const float*)src)[e];
            if (!(f >= 0.f && f < (float)n && f == floorf(f))) atomicAnd(&okf32, 0);
            double d = ((const double*)src)[e];
            if (!(d >= 0.0 && d < (double)n && d == floor(d))) atomicAnd(&okf64, 0);
        }
        __syncthreads();
        if (threadIdx.x == 0)
            g_fmt = ok64 ? 0 : (ok32 ? 1 : (okf32 ? 2 : (okf64 ? 3 : 1)));
    }
}

// ---------------- device parts ----------------
__device__ __forceinline__ void convdeg_part(const void* __restrict__ src,
                                             const void* __restrict__ dst,
                                             int e, int ecount, int n) {
    if (e >= ecount) return;
    int fmt = g_fmt;
    int s, d;
    if (fmt == 0) {
        s = (int)__ldcs((const long long*)src + e);
        d = (int)__ldcs((const long long*)dst + e);
    } else if (fmt == 1) {
        s = __ldcs((const int*)src + e);
        d = __ldcs((const int*)dst + e);
    } else if (fmt == 2) {
        s = (int)__ldcs((const float*)src + e);
        d = (int)__ldcs((const float*)dst + e);
    } else {
        s = (int)__ldcs((const double*)src + e);
        d = (int)__ldcs((const double*)dst + e);
    }
    s = s < 0 ? 0 : (s >= n ? n - 1 : s);
    d = d < 0 ? 0 : (d >= n ? n - 1 : d);
    g_esrc[e] = s;
    g_edst[e] = d;
    atomicAdd(&g_deg_out[s], 1);
    g_slot[e] = atomicAdd(&g_deg_in[d], 1);
}

__device__ __forceinline__ void gemm1_part(const float* __restrict__ X,
                                           const float* __restrict__ W1,
                                           float* __restrict__ sW1,
                                           int gblk, int n) {
    int tid = threadIdx.x;  // 256
    #pragma unroll
    for (int i = tid; i < (F_IN * HID) / 4; i += 256)
        ((float4*)sW1)[i] = ((const float4*)W1)[i];
    __syncthreads();

    int row0 = gblk * 512 + tid;
    int row1 = row0 + 256;
    if (row0 >= n) return;
    bool has1 = (row1 < n);
    int row1c = has1 ? row1 : row0;

    unsigned long long acc0[8], acc1[8];
    #pragma unroll
    for (int p = 0; p < 8; p++) { acc0[p] = 0ull; acc1[p] = 0ull; }

    const float4* xb0 = (const float4*)(X + (size_t)row0 * F_IN);
    const float4* xb1 = (const float4*)(X + (size_t)row1c * F_IN);

    for (int c = 0; c < F_IN / 4; c++) {
        float4 x0 = __ldcs(xb0 + c);
        float4 x1 = __ldcs(xb1 + c);
        const float xs0[4] = {x0.x, x0.y, x0.z, x0.w};
        const float xs1[4] = {x1.x, x1.y, x1.z, x1.w};
        #pragma unroll
        for (int k = 0; k < 4; k++) {
            unsigned long long xp0 = pack2(xs0[k]);
            unsigned long long xp1 = pack2(xs1[k]);
            const unsigned long long* w =
                (const unsigned long long*)&sW1[(4 * c + k) * HID];
            #pragma unroll
            for (int p = 0; p < 8; p++) {
                unsigned long long wp = w[p];
                fma2(acc0[p], xp0, wp);
                fma2(acc1[p], xp1, wp);
            }
        }
    }

    float* o0 = g_hpre + row0 * HID;
    #pragma unroll
    for (int p = 0; p < 8; p += 2) {
        float2 a = unpack2(acc0[p]);
        float2 b = unpack2(acc0[p + 1]);
        *(float4*)(o0 + 2 * p) = make_float4(a.x, a.y, b.x, b.y);
    }
    if (has1) {
        float* o1 = g_hpre + row1 * HID;
        #pragma unroll
        for (int p = 0; p < 8; p += 2) {
            float2 a = unpack2(acc1[p]);
            float2 b = unpack2(acc1[p + 1]);
            *(float4*)(o1 + 2 * p) = make_float4(a.x, a.y, b.x, b.y);
        }
    }
}

// ---------------- fused 1: gemm1 (blocks first) || convdeg ----------------
__global__ void __launch_bounds__(256)
k_fused1(const float* __restrict__ X, const float* __restrict__ W1,
         const void* __restrict__ src, const void* __restrict__ dst,
         int ecount, int n, int gemm_blocks) {
    __shared__ float sW1[F_IN * HID];
    if ((int)blockIdx.x < gemm_blocks) {
        gemm1_part(X, W1, sW1, blockIdx.x, n);
    } else {
        int e = (blockIdx.x - gemm_blocks) * 256 + threadIdx.x;
        convdeg_part(src, dst, e, ecount, n);
    }
}

// ---------------- single-pass scan (decoupled lookback) + norms ----------------
__global__ void __launch_bounds__(256) k_scan(int n) {
    __shared__ int wsum[8];
    __shared__ int bexcl_s;
    int tid = threadIdx.x, lane = tid & 31, wid = tid >> 5;
    int b = blockIdx.x;
    int i = b * 256 + tid;
    int v = (i < n) ? g_deg_in[i] : 0;
    int s = v;
    #pragma unroll
    for (int off = 1; off < 32; off <<= 1) {
        int t = __shfl_up_sync(0xffffffff, s, off);
        if (lane >= off) s += t;
    }
    if (lane == 31) wsum[wid] = s;
    __syncthreads();

    if (wid == 0) {
        // scan the 8 warp totals, publish aggregate, lookback, publish prefix
        int w = (lane < 8) ? wsum[lane] : 0;
        #pragma unroll
        for (int off = 1; off < 8; off <<= 1) {
            int t = __shfl_up_sync(0xffffffff, w, off);
            if (lane >= off) w += t;
        }
        if (lane < 8) wsum[lane] = w;
        int T = __shfl_sync(0xffffffff, w, 7);   // block total

        if (lane == 0) {   // publish aggregate (block 0: it's already the prefix)
            unsigned long long pk =
                ((unsigned long long)((b == 0) ? 2u : 1u) << 32) | (unsigned)T;
            *((volatile unsigned long long*)&g_lb[b]) = pk;
        }
        int running = 0;
        if (b > 0) {
            int tile = b - 1;
            while (true) {
                int idx = tile - lane;   // lane 0 = closest predecessor
                int flag, val;
                if (idx >= 0) {
                    unsigned long long x;
                    do {
                        x = *((volatile unsigned long long*)&g_lb[idx]);
                        flag = (int)(x >> 32);
                    } while (flag == 0);
                    val = (int)(unsigned)(x & 0xffffffffull);
                } else { flag = 1; val = 0; }
                unsigned mp = __ballot_sync(0xffffffff, flag == 2);
                if (mp) {
                    int first = __ffs(mp) - 1;  // closest block with prefix
                    int contrib = (lane <= first) ? val : 0;
                    #pragma unroll
                    for (int o = 16; o; o >>= 1)
                        contrib += __shfl_xor_sync(0xffffffff, contrib, o);
                    running += contrib;
                    break;
                } else {
                    int contrib = val;
                    #pragma unroll
                    for (int o = 16; o; o >>= 1)
                        contrib += __shfl_xor_sync(0xffffffff, contrib, o);
                    running += contrib;
                    tile -= 32;
                }
            }
            if (lane == 0) {
                unsigned long long pk = (2ull << 32) | (unsigned)(running + T);
                *((volatile unsigned long long*)&g_lb[b]) = pk;
            }
        }
        if (lane == 0) bexcl_s = running;
    }
    __syncthreads();

    int base = bexcl_s + ((wid > 0) ? wsum[wid - 1] : 0);
    if (i < n) {
        g_row_start[i] = base + s - v;   // global exclusive prefix
        int dout = g_deg_out[i]; if (dout < 1) dout = 1;
        int din  = v;            if (din  < 1) din  = 1;
        g_norm_src[i] = rsqrtf((float)dout);
        g_norm_dst[i] = rsqrtf((float)din);
    }
}

// ---------------- fused 2: csr fill (no atomics) || hpre scale+fp16 ----------------
__global__ void __launch_bounds__(256)
k_fused2(int ecount, int n, int csr_blocks) {
    if ((int)blockIdx.x < csr_blocks) {
        int e = blockIdx.x * 256 + threadIdx.x;
        if (e < ecount) {
            int d = __ldcs(&g_edst[e]);
            int s = __ldcs(&g_esrc[e]);
            int sl = __ldcs(&g_slot[e]);
            g_csr[g_row_start[d] + sl] = s;
        }
    } else {
        int i = (blockIdx.x - csr_blocks) * 256 + threadIdx.x;  // uint2 index
        if (i < n * 4) {
            float ns = g_norm_src[i >> 2];
            float4 v = *((const float4*)g_hpre + i);
            g_hpreh[i] = pack_half4(v.x * ns, v.y * ns, v.z * ns, v.w * ns);
        }
    }
}

// ---------------- SpMM stage 1: g_hmidh = relu(spmm(g_hpreh)*nd + b1)*ns ----------------
__global__ void k_spmm1(const float* __restrict__ b1, int n, int ecount) {
    int warp = (blockIdx.x * blockDim.x + threadIdx.x) >> 5;
    if (warp >= n) return;
    int lane = threadIdx.x & 31;
    int sub = lane & 3;
    int grp = lane >> 2;
    int v = warp;
    int start = g_row_start[v];
    int end = (v + 1 < n) ? g_row_start[v + 1] : ecount;

    float ax = 0.f, ay = 0.f, az = 0.f, aw = 0.f;
    int e = start + grp;
    int scur = (e < end) ? __ldg(&g_csr[e]) : 0;
    for (; e < end; e += 8) {
        int snext = (e + 8 < end) ? __ldg(&g_csr[e + 8]) : 0;
        uint2 q = g_hpreh[scur * 4 + sub];
        float2 f0 = __half22float2(*(__half2*)&q.x);
        float2 f1 = __half22float2(*(__half2*)&q.y);
        ax += f0.x; ay += f0.y; az += f1.x; aw += f1.y;
        scur = snext;
    }
    #pragma unroll
    for (int off = 4; off < 32; off <<= 1) {
        ax += __shfl_xor_sync(0xffffffff, ax, off);
        ay += __shfl_xor_sync(0xffffffff, ay, off);
        az += __shfl_xor_sync(0xffffffff, az, off);
        aw += __shfl_xor_sync(0xffffffff, aw, off);
    }
    if (lane < 4) {
        float nd = g_norm_dst[v];
        float ns = g_norm_src[v];
        float4 bb = ((const float4*)b1)[lane];
        float rx = fmaxf(ax * nd + bb.x, 0.f) * ns;
        float ry = fmaxf(ay * nd + bb.y, 0.f) * ns;
        float rz = fmaxf(az * nd + bb.z, 0.f) * ns;
        float rw = fmaxf(aw * nd + bb.w, 0.f) * ns;
        g_hmidh[v * 4 + lane] = pack_half4(rx, ry, rz, rw);
    }
}

// ---------------- SpMM stage 2 + GEMM2 fused ----------------
__global__ void k_spmm2g2(const float* __restrict__ W2,
                          const float* __restrict__ b2,
                          float* __restrict__ out, int n, int ecount) {
    __shared__ float sW2[HID * NLAB];
    __shared__ float sb2[NLAB];
    int tid = threadIdx.x;  // 256
    for (int i = tid; i < HID * NLAB; i += 256) sW2[i] = W2[i];
    if (tid < NLAB) sb2[tid] = b2[tid];
    __syncthreads();

    int warp = (blockIdx.x * 256 + tid) >> 5;
    if (warp >= n) return;
    int lane = tid & 31;
    int sub = lane & 3;
    int grp = lane >> 2;
    int v = warp;
    int start = g_row_start[v];
    int end = (v + 1 < n) ? g_row_start[v + 1] : ecount;

    float ax = 0.f, ay = 0.f, az = 0.f, aw = 0.f;
    int e = start + grp;
    int scur = (e < end) ? __ldg(&g_csr[e]) : 0;
    for (; e < end; e += 8) {
        int snext = (e + 8 < end) ? __ldg(&g_csr[e + 8]) : 0;
        uint2 q = g_hmidh[scur * 4 + sub];
        float2 f0 = __half22float2(*(__half2*)&q.x);
        float2 f1 = __half22float2(*(__half2*)&q.y);
        ax += f0.x; ay += f0.y; az += f1.x; aw += f1.y;
        scur = snext;
    }
    #pragma unroll
    for (int off = 4; off < 32; off <<= 1) {
        ax += __shfl_xor_sync(0xffffffff, ax, off);
        ay += __shfl_xor_sync(0xffffffff, ay, off);
        az += __shfl_xor_sync(0xffffffff, az, off);
        aw += __shfl_xor_sync(0xffffffff, aw, off);
    }
    float nd = g_norm_dst[v];
    float h[HID];
    #pragma unroll
    for (int j = 0; j < 4; j++) {
        h[4 * j + 0] = __shfl_sync(0xffffffff, ax, j) * nd;
        h[4 * j + 1] = __shfl_sync(0xffffffff, ay, j) * nd;
        h[4 * j + 2] = __shfl_sync(0xffffffff, az, j) * nd;
        h[4 * j + 3] = __shfl_sync(0xffffffff, aw, j) * nd;
    }
    float acc0 = sb2[lane];
    float acc1 = sb2[lane + 32];
    #pragma unroll
    for (int k = 0; k < HID; k++) {
        acc0 += h[k] * sW2[k * NLAB + lane];
        acc1 += h[k] * sW2[k * NLAB + lane + 32];
    }
    out[v * NLAB + lane]      = acc0;
    out[v * NLAB + lane + 32] = acc1;
}

// ---------------- launch ----------------
extern "C" void kernel_launch(void* const* d_in, const int* in_sizes, int n_in,
                              void* d_out, int out_size) {
    int n = out_size / NLAB;
    if (n > NMAX) n = NMAX;

    // Identify inputs by element-count signature.
    int idx_X = -1, idx_W1 = -1, idx_b1 = -1, idx_W2 = -1, idx_b2 = -1;
    int idx_e1 = -1, idx_e2 = -1;
    for (int i = 0; i < n_in; i++) {
        int sz = in_sizes[i];
        if (sz == n * F_IN)            idx_X = i;
        else if (sz == F_IN * HID)     idx_W1 = i;
        else if (sz == HID)            idx_b1 = i;
        else if (sz == HID * NLAB)     idx_W2 = i;
        else if (sz == NLAB)           idx_b2 = i;
        else if (idx_e1 < 0)           idx_e1 = i;
        else                           idx_e2 = i;
    }

    // src/dst by ordering convention (see round-3 notes).
    int idx_src, idx_dst;
    if (idx_e1 > idx_X) { idx_src = idx_e1; idx_dst = idx_e2; }
    else                { idx_dst = idx_e1; idx_src = idx_e2; }

    const float* X   = (const float*)d_in[idx_X];
    const float* W1  = (const float*)d_in[idx_W1];
    const float* b1  = (const float*)d_in[idx_b1];
    const float* W2  = (const float*)d_in[idx_W2];
    const float* b2  = (const float*)d_in[idx_b2];
    const void*  esrc = d_in[idx_src];
    const void*  edst = d_in[idx_dst];

    int ecount = in_sizes[idx_src];
    if (ecount > EMAX) ecount = EMAX;

    int gb256_n = (n + 255) / 256;
    int gb256_e = (ecount + 255) / 256;
    int gemm_blocks = (n + 511) / 512;
    int scale_blocks = (n * 4 + 255) / 256;

    k_init<<<gb256_n, 256>>>(esrc, ecount, n);
    k_fused1<<<gemm_blocks + gb256_e, 256>>>(X, W1, esrc, edst,
                                             ecount, n, gemm_blocks);
    k_scan<<<gb256_n, 256>>>(n);
    k_fused2<<<gb256_e + scale_blocks, 256>>>(ecount, n, gb256_e);

    int spmm_blocks = (n * 32 + 255) / 256;
    k_spmm1<<<spmm_blocks, 256>>>(b1, n, ecount);
    k_spmm2g2<<<spmm_blocks, 256>>>(W2, b2, (float*)d_out, n, ecount);
}